// round 2
// baseline (speedup 1.0000x reference)
#include <cuda_runtime.h>
#include <cstdint>

#define N_NODES 100000
#define N_EDGES 1250000
#define DIM 64
#define NBASES 16

// ---------------- scratch (device globals; no allocation allowed) ----------
__device__ float g_S[(size_t)N_NODES * DIM];   // scatter-sum of x[src] per dst
__device__ float g_deg[N_NODES];               // in-degree (as float)
__device__ float g_B[128 * DIM];               // [W_msg ; W_self] stacked (K=128, N=64)
__device__ float g_bm[DIM];
__device__ float g_bs[DIM];

// ---------------- kernel 1: zero scratch ----------------------------------
__global__ void zero_kernel() {
    size_t i = (size_t)blockIdx.x * blockDim.x + threadIdx.x;
    const size_t tot4 = (size_t)N_NODES * DIM / 4;  // 1.6M float4
    if (i < tot4) reinterpret_cast<float4*>(g_S)[i] = make_float4(0.f, 0.f, 0.f, 0.f);
    if (i < N_NODES) g_deg[i] = 0.f;
}

// ---------------- kernel 2: collapse bases into weights -------------------
__global__ void weights_kernel(const float* __restrict__ wm,
                               const float* __restrict__ bm,
                               const float* __restrict__ ws,
                               const float* __restrict__ bs,
                               const float* __restrict__ lc) {
    __shared__ float c[NBASES];
    if (threadIdx.x < NBASES) c[threadIdx.x] = lc[threadIdx.x];
    __syncthreads();
    int tid = threadIdx.x;  // 256 threads
    for (int idx = tid; idx < 64 * 64; idx += 256) {
        float sm = 0.f, ss = 0.f;
        #pragma unroll
        for (int b = 0; b < NBASES; b++) {
            sm = fmaf(wm[idx * NBASES + b], c[b], sm);
            ss = fmaf(ws[idx * NBASES + b], c[b], ss);
        }
        // idx = i*64 + o ; B row k=i (msg) / k=i+64 (self), col o
        g_B[idx]        = sm;
        g_B[4096 + idx] = ss;
    }
    if (tid < DIM) {
        float am = 0.f, as = 0.f;
        #pragma unroll
        for (int b = 0; b < NBASES; b++) {
            am = fmaf(bm[tid * NBASES + b], c[b], am);
            as = fmaf(bs[tid * NBASES + b], c[b], as);
        }
        g_bm[tid] = am;
        g_bs[tid] = as;
    }
}

// ---------------- kernel 3: edge scatter (S[dst] += x[src], deg[dst]++) ----
// 16 threads per edge, each handling one float4 of the 64-float row.
__global__ __launch_bounds__(256) void scatter_kernel(
    const float4* __restrict__ x4, const int* __restrict__ ei) {
    int t = blockIdx.x * blockDim.x + threadIdx.x;
    int e = t >> 4;
    if (e >= N_EDGES) return;
    int sub = t & 15;
    int src = __ldg(&ei[e]);
    int dst = __ldg(&ei[N_EDGES + e]);
    float4 v = __ldg(&x4[(size_t)src * 16 + sub]);
    float* p = &g_S[(size_t)dst * DIM + sub * 4];
    asm volatile("red.global.add.v4.f32 [%0], {%1, %2, %3, %4};"
                 :: "l"(p), "f"(v.x), "f"(v.y), "f"(v.z), "f"(v.w)
                 : "memory");
    if (sub == 0) atomicAdd(&g_deg[dst], 1.0f);
}

// ---------------- kernel 4: out = [S|x] @ [Wm;Ws] + deg*bm + bs, L2-norm ---
// Tile: 64 nodes x 64 cols, K=128. 256 threads, 4x4 register blocking.
// A tile staged in STATIC shared memory (33.8KB); B read via __ldg (32KB,
// L1-resident after first tile). No dynamic smem, no attribute calls.
#define SA_STRIDE 132                    // 128 + 4 pad (16B-aligned, bank-shifted)
#define N_TILES ((N_NODES + 63) / 64)    // 1563 (last tile partial)

__global__ __launch_bounds__(256) void out_kernel(const float* __restrict__ x,
                                                  float* __restrict__ out) {
    __shared__ float sA[64 * SA_STRIDE];  // 33792 B

    int tid = threadIdx.x;

    const int jj = tid & 15;   // column group: cols j0..j0+3
    const int nn = tid >> 4;   // node group:  rows n0..n0+3
    const int j0 = jj * 4;
    const int n0 = nn * 4;

    // biases for this thread's 4 columns (uniform per thread, kept in regs)
    float bmj[4], bsj[4];
    #pragma unroll
    for (int c = 0; c < 4; c++) {
        bmj[c] = __ldg(&g_bm[j0 + c]);
        bsj[c] = __ldg(&g_bs[j0 + c]);
    }

    for (int t = blockIdx.x; t < N_TILES; t += gridDim.x) {
        const int node0 = t * 64;
        // Stage A tile: 64 rows x 128 cols; cols 0-63 from S, 64-127 from x.
        for (int v = tid; v < 64 * 32; v += 256) {
            int row  = v >> 5;       // 32 float4 per row
            int col4 = v & 31;
            int node = node0 + row;
            float4 val = make_float4(0.f, 0.f, 0.f, 0.f);
            if (node < N_NODES) {
                if (col4 < 16)
                    val = reinterpret_cast<const float4*>(g_S)[(size_t)node * 16 + col4];
                else
                    val = __ldg(&reinterpret_cast<const float4*>(x)[(size_t)node * 16 + (col4 - 16)]);
            }
            *reinterpret_cast<float4*>(&sA[row * SA_STRIDE + col4 * 4]) = val;
        }
        __syncthreads();

        float acc[4][4] = {};
        #pragma unroll 4
        for (int k4 = 0; k4 < 32; k4++) {
            float ar[4][4], bk[4][4];
            #pragma unroll
            for (int r = 0; r < 4; r++)
                *reinterpret_cast<float4*>(ar[r]) =
                    *reinterpret_cast<const float4*>(&sA[(n0 + r) * SA_STRIDE + k4 * 4]);
            #pragma unroll
            for (int kk = 0; kk < 4; kk++)
                *reinterpret_cast<float4*>(bk[kk]) =
                    __ldg(reinterpret_cast<const float4*>(&g_B[(k4 * 4 + kk) * 64 + j0]));
            #pragma unroll
            for (int r = 0; r < 4; r++)
                #pragma unroll
                for (int kk = 0; kk < 4; kk++)
                    #pragma unroll
                    for (int c = 0; c < 4; c++)
                        acc[r][c] = fmaf(ar[r][kk], bk[kk][c], acc[r][c]);
        }

        // Epilogue: bias, row L2-norm (reduce across the 16 jj lanes), store.
        #pragma unroll
        for (int r = 0; r < 4; r++) {
            int node = node0 + n0 + r;
            float deg = (node < N_NODES) ? __ldg(&g_deg[node]) : 0.f;
            float o[4];
            #pragma unroll
            for (int c = 0; c < 4; c++)
                o[c] = acc[r][c] + deg * bmj[c] + bsj[c];
            float ss = o[0] * o[0] + o[1] * o[1] + o[2] * o[2] + o[3] * o[3];
            #pragma unroll
            for (int off = 8; off > 0; off >>= 1)
                ss += __shfl_xor_sync(0xffffffffu, ss, off);
            float inv = 1.0f / fmaxf(sqrtf(ss), 1e-12f);
            if (node < N_NODES) {
                float4 ov = make_float4(o[0] * inv, o[1] * inv, o[2] * inv, o[3] * inv);
                reinterpret_cast<float4*>(out)[(size_t)node * 16 + jj] = ov;
            }
        }
        __syncthreads();  // protect sA before next tile's staging
    }
}

// ---------------- launch ----------------------------------------------------
extern "C" void kernel_launch(void* const* d_in, const int* in_sizes, int n_in,
                              void* d_out, int out_size) {
    const float* x   = (const float*)d_in[0];
    const int*   ei  = (const int*)d_in[1];
    const float* wm  = (const float*)d_in[2];
    const float* bm  = (const float*)d_in[3];
    const float* ws  = (const float*)d_in[4];
    const float* bs  = (const float*)d_in[5];
    const float* lc  = (const float*)d_in[6];
    float* out = (float*)d_out;

    // zero scratch (1.6M float4 + deg covered by same grid)
    {
        int threads = 256;
        size_t tot = (size_t)N_NODES * DIM / 4;  // 1,600,000
        int blocks = (int)((tot + threads - 1) / threads);
        zero_kernel<<<blocks, threads>>>();
    }
    // collapse bases
    weights_kernel<<<1, 256>>>(wm, bm, ws, bs, lc);
    // edge scatter
    {
        long long tot = (long long)N_EDGES * 16;
        int blocks = (int)((tot + 255) / 256);
        scatter_kernel<<<blocks, 256>>>((const float4*)x, ei);
    }
    // fused GEMM + bias + normalize (static smem, 592 persistent-ish blocks)
    out_kernel<<<592, 256>>>(x, out);
}

// round 4
// speedup vs baseline: 1.0479x; 1.0479x over previous
#include <cuda_runtime.h>
#include <cstdint>

#define N_NODES 100000
#define N_EDGES 1250000
#define DIM 64
#define NBASES 16
#define E_HALF (N_EDGES / 2)
#define N_TILES ((N_NODES + 63) / 64)   // 1563

// ---------------- scratch (device globals; no allocation allowed) ----------
__device__ float g_S[(size_t)N_NODES * DIM];          // scatter-sum of x[src]; self-zeroed by out_kernel
__device__ float g_deg[N_NODES];                      // in-degree; self-zeroed by out_kernel
__device__ __align__(16) float2 g_Bp[64 * 64];        // k-pair-packed B: [kp][c] = (B[2kp][c], B[2kp+1][c])
__device__ float g_bm[DIM];
__device__ float g_bs[DIM];

// packed f32x2 FMA: d.lo += a.lo*b.lo ; d.hi += a.hi*b.hi
__device__ __forceinline__ void fma2(unsigned long long& d,
                                     unsigned long long a,
                                     unsigned long long b) {
    asm("fma.rn.f32x2 %0, %1, %2, %0;" : "+l"(d) : "l"(a), "l"(b));
}
__device__ __forceinline__ float pair_sum(unsigned long long v) {
    return __uint_as_float((unsigned)(v & 0xffffffffull)) +
           __uint_as_float((unsigned)(v >> 32));
}

// ---------------- kernel 1: collapse bases into packed weights -------------
__global__ void weights_kernel(const float* __restrict__ wm,
                               const float* __restrict__ bm,
                               const float* __restrict__ ws,
                               const float* __restrict__ bs,
                               const float* __restrict__ lc) {
    __shared__ float c[NBASES];
    if (threadIdx.x < NBASES) c[threadIdx.x] = lc[threadIdx.x];
    __syncthreads();
    int tid = threadIdx.x;  // 256 threads
    // B rows k: 0..63 = W_msg (i=k), 64..127 = W_self (i=k-64).
    // Packed: g_Bp[kp*64+o] = (B[2kp][o], B[2kp+1][o]), kp in [0,64).
    for (int idx = tid; idx < 64 * 64; idx += 256) {
        int kp = idx >> 6;
        int o  = idx & 63;
        const float* base = (kp < 32) ? wm : ws;
        int i0 = (kp < 32) ? 2 * kp : 2 * (kp - 32);
        float lo = 0.f, hi = 0.f;
        const float* p0 = &base[((size_t)i0 * 64 + o) * NBASES];
        const float* p1 = &base[((size_t)(i0 + 1) * 64 + o) * NBASES];
        #pragma unroll
        for (int b = 0; b < NBASES; b++) {
            lo = fmaf(p0[b], c[b], lo);
            hi = fmaf(p1[b], c[b], hi);
        }
        g_Bp[idx] = make_float2(lo, hi);
    }
    if (tid < DIM) {
        float am = 0.f, as = 0.f;
        #pragma unroll
        for (int b = 0; b < NBASES; b++) {
            am = fmaf(bm[tid * NBASES + b], c[b], am);
            as = fmaf(bs[tid * NBASES + b], c[b], as);
        }
        g_bm[tid] = am;
        g_bs[tid] = as;
    }
}

// ---------------- kernel 2: edge scatter (S[dst] += x[src], deg[dst]++) ----
// 16 threads per edge-PAIR (edges e and e+E_HALF), float4 granularity, ILP 2.
__global__ __launch_bounds__(256) void scatter_kernel(
    const float4* __restrict__ x4, const int* __restrict__ ei) {
    int t = blockIdx.x * blockDim.x + threadIdx.x;
    int e = t >> 4;
    if (e >= E_HALF) return;
    int sub = t & 15;
    int e2 = e + E_HALF;
    int src1 = __ldg(&ei[e]);
    int dst1 = __ldg(&ei[N_EDGES + e]);
    int src2 = __ldg(&ei[e2]);
    int dst2 = __ldg(&ei[N_EDGES + e2]);
    float4 v1 = __ldg(&x4[(size_t)src1 * 16 + sub]);
    float4 v2 = __ldg(&x4[(size_t)src2 * 16 + sub]);
    float* p1 = &g_S[(size_t)dst1 * DIM + sub * 4];
    float* p2 = &g_S[(size_t)dst2 * DIM + sub * 4];
    asm volatile("red.global.add.v4.f32 [%0], {%1, %2, %3, %4};"
                 :: "l"(p1), "f"(v1.x), "f"(v1.y), "f"(v1.z), "f"(v1.w) : "memory");
    asm volatile("red.global.add.v4.f32 [%0], {%1, %2, %3, %4};"
                 :: "l"(p2), "f"(v2.x), "f"(v2.y), "f"(v2.z), "f"(v2.w) : "memory");
    if (sub == 0) {
        atomicAdd(&g_deg[dst1], 1.0f);
        atomicAdd(&g_deg[dst2], 1.0f);
    }
}

// ---------------- kernel 3: out = [S|x] @ [Wm;Ws] + deg*bm + bs, L2-norm ---
// One block per 64-node tile. 256 threads, each 4 rows x 4 cols.
// No shared memory, no barriers: A rows read directly (L2-resident), B from
// k-pair-packed g_Bp (L1-resident). Even/odd k live in f32x2 halves.
// Self-cleans: zeroes its tile's g_S rows + g_deg after consumption.
__global__ __launch_bounds__(256, 2) void out_kernel(const float* __restrict__ x,
                                                     float* __restrict__ out) {
    const int tid = threadIdx.x;
    const int jj = tid & 15;   // column group: cols j0..j0+3
    const int nn = tid >> 4;   // row group:   rows n0..n0+3
    const int j0 = jj * 4;
    const int n0 = nn * 4;
    const int node0 = blockIdx.x * 64;

    const ulonglong2* __restrict__ S2  = reinterpret_cast<const ulonglong2*>(g_S);
    const ulonglong2* __restrict__ X2  = reinterpret_cast<const ulonglong2*>(x);
    const ulonglong2* __restrict__ Bp2 = reinterpret_cast<const ulonglong2*>(g_Bp);
    const int bbase = j0 >> 1;  // ull2 index within a Bp row (32 ull2/row)

    bool valid[4];
    int node[4];
    #pragma unroll
    for (int r = 0; r < 4; r++) {
        node[r] = node0 + n0 + r;
        valid[r] = node[r] < N_NODES;
    }

    unsigned long long acc[4][4];
    #pragma unroll
    for (int r = 0; r < 4; r++)
        #pragma unroll
        for (int c2 = 0; c2 < 4; c2++) acc[r][c2] = 0ull;

    const ulonglong2 zz = make_ulonglong2(0ull, 0ull);

    // ---- K half 1: A = S rows (k 0..63), B pair-rows kp 0..31 ----
    #pragma unroll 4
    for (int k4 = 0; k4 < 16; k4++) {
        ulonglong2 av[4];
        #pragma unroll
        for (int r = 0; r < 4; r++)
            av[r] = valid[r] ? __ldg(&S2[(size_t)node[r] * 16 + k4]) : zz;
        #pragma unroll
        for (int p = 0; p < 2; p++) {
            int kp = k4 * 2 + p;                       // k = 4k4+2p, 4k4+2p+1
            ulonglong2 b01 = __ldg(&Bp2[kp * 32 + bbase]);
            ulonglong2 b23 = __ldg(&Bp2[kp * 32 + bbase + 1]);
            #pragma unroll
            for (int r = 0; r < 4; r++) {
                unsigned long long a = p ? av[r].y : av[r].x;
                fma2(acc[r][0], a, b01.x);
                fma2(acc[r][1], a, b01.y);
                fma2(acc[r][2], a, b23.x);
                fma2(acc[r][3], a, b23.y);
            }
        }
    }
    // ---- K half 2: A = x rows (k 64..127), B pair-rows kp 32..63 ----
    #pragma unroll 4
    for (int k4 = 0; k4 < 16; k4++) {
        ulonglong2 av[4];
        #pragma unroll
        for (int r = 0; r < 4; r++)
            av[r] = valid[r] ? __ldg(&X2[(size_t)node[r] * 16 + k4]) : zz;
        #pragma unroll
        for (int p = 0; p < 2; p++) {
            int kp = 32 + k4 * 2 + p;                  // FIX: pair-row index (was 64 + ...)
            ulonglong2 b01 = __ldg(&Bp2[kp * 32 + bbase]);
            ulonglong2 b23 = __ldg(&Bp2[kp * 32 + bbase + 1]);
            #pragma unroll
            for (int r = 0; r < 4; r++) {
                unsigned long long a = p ? av[r].y : av[r].x;
                fma2(acc[r][0], a, b01.x);
                fma2(acc[r][1], a, b01.y);
                fma2(acc[r][2], a, b23.x);
                fma2(acc[r][3], a, b23.y);
            }
        }
    }

    // biases for this thread's 4 columns
    float bmj[4], bsj[4];
    #pragma unroll
    for (int c = 0; c < 4; c++) {
        bmj[c] = __ldg(&g_bm[j0 + c]);
        bsj[c] = __ldg(&g_bs[j0 + c]);
    }

    // Epilogue: fold halves, bias, row L2-norm (reduce across 16 jj lanes), store.
    #pragma unroll
    for (int r = 0; r < 4; r++) {
        float deg = valid[r] ? __ldg(&g_deg[node[r]]) : 0.f;
        float o[4];
        #pragma unroll
        for (int c = 0; c < 4; c++)
            o[c] = pair_sum(acc[r][c]) + deg * bmj[c] + bsj[c];
        float ss = o[0] * o[0] + o[1] * o[1] + o[2] * o[2] + o[3] * o[3];
        #pragma unroll
        for (int off = 8; off > 0; off >>= 1)
            ss += __shfl_xor_sync(0xffffffffu, ss, off);   // stays within 16-lane half
        float inv = 1.0f / fmaxf(sqrtf(ss), 1e-12f);
        if (valid[r]) {
            float4 ov = make_float4(o[0] * inv, o[1] * inv, o[2] * inv, o[3] * inv);
            reinterpret_cast<float4*>(out)[(size_t)node[r] * 16 + jj] = ov;
        }
    }

    // Self-clean scratch for the next launch. All reads of these rows happened
    // above in this same 16-thread group; the shuffles ordered them.
    float4* S4 = reinterpret_cast<float4*>(g_S);
    #pragma unroll
    for (int r = 0; r < 4; r++) {
        if (valid[r]) {
            S4[(size_t)node[r] * 16 + jj] = make_float4(0.f, 0.f, 0.f, 0.f);
            if (jj == 0) g_deg[node[r]] = 0.f;
        }
    }
}

// ---------------- launch ----------------------------------------------------
extern "C" void kernel_launch(void* const* d_in, const int* in_sizes, int n_in,
                              void* d_out, int out_size) {
    const float* x  = (const float*)d_in[0];
    const int*   ei = (const int*)d_in[1];
    const float* wm = (const float*)d_in[2];
    const float* bm = (const float*)d_in[3];
    const float* ws = (const float*)d_in[4];
    const float* bs = (const float*)d_in[5];
    const float* lc = (const float*)d_in[6];
    float* out = (float*)d_out;

    // collapse bases into packed weights
    weights_kernel<<<1, 256>>>(wm, bm, ws, bs, lc);
    // edge scatter (g_S/g_deg are zero: BSS init on first call, self-cleaned after)
    {
        long long tot = (long long)E_HALF * 16;            // 10M threads
        int blocks = (int)((tot + 255) / 256);
        scatter_kernel<<<blocks, 256>>>((const float4*)x, ei);
    }
    // fused GEMM + bias + normalize + scratch self-clean
    out_kernel<<<N_TILES, 256>>>(x, out);
}

// round 5
// speedup vs baseline: 1.2935x; 1.2344x over previous
#include <cuda_runtime.h>
#include <cstdint>

#define N_NODES 100000
#define N_EDGES 1250000
#define DIM 64
#define NBASES 16
#define E_HALF (N_EDGES / 2)
#define N_TILES ((N_NODES + 63) / 64)   // 1563

// ---------------- scratch (device globals; no allocation allowed) ----------
__device__ float g_S[(size_t)N_NODES * DIM];          // scatter-sum of x[src]; self-zeroed by out_kernel
__device__ float g_deg[N_NODES];                      // in-degree; self-zeroed by out_kernel
__device__ __align__(16) float2 g_Bp[64 * 64];        // k-pair-packed B: [kp][c] = (B[2kp][c], B[2kp+1][c])
__device__ float g_bm[DIM];
__device__ float g_bs[DIM];

// packed f32x2 FMA: d.lo += a.lo*b.lo ; d.hi += a.hi*b.hi
__device__ __forceinline__ void fma2(unsigned long long& d,
                                     unsigned long long a,
                                     unsigned long long b) {
    asm("fma.rn.f32x2 %0, %1, %2, %0;" : "+l"(d) : "l"(a), "l"(b));
}
__device__ __forceinline__ float pair_sum(unsigned long long v) {
    return __uint_as_float((unsigned)(v & 0xffffffffull)) +
           __uint_as_float((unsigned)(v >> 32));
}

// ---------------- kernel 1: collapse bases into packed weights -------------
// PARALLELIZED: 17 blocks x 256 threads. Blocks 0..15 each produce 256 of the
// 4096 packed-B elements (one per thread); block 16 does the biases.
// Round-4 ncu showed the old grid=1 version latency-bound at 39.6us.
__global__ __launch_bounds__(256) void weights_kernel(
    const float* __restrict__ wm, const float* __restrict__ bm,
    const float* __restrict__ ws, const float* __restrict__ bs,
    const float* __restrict__ lc) {
    __shared__ float c[NBASES];
    if (threadIdx.x < NBASES) c[threadIdx.x] = lc[threadIdx.x];
    __syncthreads();

    if (blockIdx.x < 16) {
        int idx = blockIdx.x * 256 + threadIdx.x;   // 0..4095
        int kp = idx >> 6;
        int o  = idx & 63;
        const float* base = (kp < 32) ? wm : ws;
        int i0 = (kp < 32) ? 2 * kp : 2 * (kp - 32);
        const float4* p0 = reinterpret_cast<const float4*>(&base[((size_t)i0 * 64 + o) * NBASES]);
        const float4* p1 = reinterpret_cast<const float4*>(&base[((size_t)(i0 + 1) * 64 + o) * NBASES]);
        float lo = 0.f, hi = 0.f;
        #pragma unroll
        for (int q = 0; q < 4; q++) {               // 16 bases as 4x float4 (MLP)
            float4 a0 = __ldg(&p0[q]);
            float4 a1 = __ldg(&p1[q]);
            lo = fmaf(a0.x, c[4*q+0], lo); lo = fmaf(a0.y, c[4*q+1], lo);
            lo = fmaf(a0.z, c[4*q+2], lo); lo = fmaf(a0.w, c[4*q+3], lo);
            hi = fmaf(a1.x, c[4*q+0], hi); hi = fmaf(a1.y, c[4*q+1], hi);
            hi = fmaf(a1.z, c[4*q+2], hi); hi = fmaf(a1.w, c[4*q+3], hi);
        }
        g_Bp[idx] = make_float2(lo, hi);
    } else if (threadIdx.x < DIM) {
        int tid = threadIdx.x;
        float am = 0.f, as = 0.f;
        #pragma unroll
        for (int b = 0; b < NBASES; b++) {
            am = fmaf(__ldg(&bm[tid * NBASES + b]), c[b], am);
            as = fmaf(__ldg(&bs[tid * NBASES + b]), c[b], as);
        }
        g_bm[tid] = am;
        g_bs[tid] = as;
    }
}

// ---------------- kernel 2: edge scatter (S[dst] += x[src], deg[dst]++) ----
// 16 threads per edge-PAIR (edges e and e+E_HALF), float4 granularity, ILP 2.
__global__ __launch_bounds__(256) void scatter_kernel(
    const float4* __restrict__ x4, const int* __restrict__ ei) {
    int t = blockIdx.x * blockDim.x + threadIdx.x;
    int e = t >> 4;
    if (e >= E_HALF) return;
    int sub = t & 15;
    int e2 = e + E_HALF;
    int src1 = __ldg(&ei[e]);
    int dst1 = __ldg(&ei[N_EDGES + e]);
    int src2 = __ldg(&ei[e2]);
    int dst2 = __ldg(&ei[N_EDGES + e2]);
    float4 v1 = __ldg(&x4[(size_t)src1 * 16 + sub]);
    float4 v2 = __ldg(&x4[(size_t)src2 * 16 + sub]);
    float* p1 = &g_S[(size_t)dst1 * DIM + sub * 4];
    float* p2 = &g_S[(size_t)dst2 * DIM + sub * 4];
    asm volatile("red.global.add.v4.f32 [%0], {%1, %2, %3, %4};"
                 :: "l"(p1), "f"(v1.x), "f"(v1.y), "f"(v1.z), "f"(v1.w) : "memory");
    asm volatile("red.global.add.v4.f32 [%0], {%1, %2, %3, %4};"
                 :: "l"(p2), "f"(v2.x), "f"(v2.y), "f"(v2.z), "f"(v2.w) : "memory");
    if (sub == 0) {
        atomicAdd(&g_deg[dst1], 1.0f);
        atomicAdd(&g_deg[dst2], 1.0f);
    }
}

// ---------------- kernel 3: out = [S|x] @ [Wm;Ws] + deg*bm + bs, L2-norm ---
// One block per 64-node tile. 256 threads, each 4 rows x 4 cols.
// No shared memory, no barriers: A rows read directly (L2-resident), B from
// k-pair-packed g_Bp (L1-resident). Even/odd k live in f32x2 halves.
// Self-cleans: zeroes its tile's g_S rows + g_deg after consumption.
__global__ __launch_bounds__(256, 2) void out_kernel(const float* __restrict__ x,
                                                     float* __restrict__ out) {
    const int tid = threadIdx.x;
    const int jj = tid & 15;   // column group: cols j0..j0+3
    const int nn = tid >> 4;   // row group:   rows n0..n0+3
    const int j0 = jj * 4;
    const int n0 = nn * 4;
    const int node0 = blockIdx.x * 64;

    const ulonglong2* __restrict__ S2  = reinterpret_cast<const ulonglong2*>(g_S);
    const ulonglong2* __restrict__ X2  = reinterpret_cast<const ulonglong2*>(x);
    const ulonglong2* __restrict__ Bp2 = reinterpret_cast<const ulonglong2*>(g_Bp);
    const int bbase = j0 >> 1;  // ull2 index within a Bp row (32 ull2/row)

    bool valid[4];
    int node[4];
    #pragma unroll
    for (int r = 0; r < 4; r++) {
        node[r] = node0 + n0 + r;
        valid[r] = node[r] < N_NODES;
    }

    unsigned long long acc[4][4];
    #pragma unroll
    for (int r = 0; r < 4; r++)
        #pragma unroll
        for (int c2 = 0; c2 < 4; c2++) acc[r][c2] = 0ull;

    const ulonglong2 zz = make_ulonglong2(0ull, 0ull);

    // ---- K half 1: A = S rows (k 0..63), B pair-rows kp 0..31 ----
    #pragma unroll 4
    for (int k4 = 0; k4 < 16; k4++) {
        ulonglong2 av[4];
        #pragma unroll
        for (int r = 0; r < 4; r++)
            av[r] = valid[r] ? __ldg(&S2[(size_t)node[r] * 16 + k4]) : zz;
        #pragma unroll
        for (int p = 0; p < 2; p++) {
            int kp = k4 * 2 + p;
            ulonglong2 b01 = __ldg(&Bp2[kp * 32 + bbase]);
            ulonglong2 b23 = __ldg(&Bp2[kp * 32 + bbase + 1]);
            #pragma unroll
            for (int r = 0; r < 4; r++) {
                unsigned long long a = p ? av[r].y : av[r].x;
                fma2(acc[r][0], a, b01.x);
                fma2(acc[r][1], a, b01.y);
                fma2(acc[r][2], a, b23.x);
                fma2(acc[r][3], a, b23.y);
            }
        }
    }
    // ---- K half 2: A = x rows (k 64..127), B pair-rows kp 32..63 ----
    #pragma unroll 4
    for (int k4 = 0; k4 < 16; k4++) {
        ulonglong2 av[4];
        #pragma unroll
        for (int r = 0; r < 4; r++)
            av[r] = valid[r] ? __ldg(&X2[(size_t)node[r] * 16 + k4]) : zz;
        #pragma unroll
        for (int p = 0; p < 2; p++) {
            int kp = 32 + k4 * 2 + p;
            ulonglong2 b01 = __ldg(&Bp2[kp * 32 + bbase]);
            ulonglong2 b23 = __ldg(&Bp2[kp * 32 + bbase + 1]);
            #pragma unroll
            for (int r = 0; r < 4; r++) {
                unsigned long long a = p ? av[r].y : av[r].x;
                fma2(acc[r][0], a, b01.x);
                fma2(acc[r][1], a, b01.y);
                fma2(acc[r][2], a, b23.x);
                fma2(acc[r][3], a, b23.y);
            }
        }
    }

    // biases for this thread's 4 columns
    float bmj[4], bsj[4];
    #pragma unroll
    for (int c = 0; c < 4; c++) {
        bmj[c] = __ldg(&g_bm[j0 + c]);
        bsj[c] = __ldg(&g_bs[j0 + c]);
    }

    // Epilogue: fold halves, bias, row L2-norm (reduce across 16 jj lanes), store.
    #pragma unroll
    for (int r = 0; r < 4; r++) {
        float deg = valid[r] ? __ldg(&g_deg[node[r]]) : 0.f;
        float o[4];
        #pragma unroll
        for (int c = 0; c < 4; c++)
            o[c] = pair_sum(acc[r][c]) + deg * bmj[c] + bsj[c];
        float ss = o[0] * o[0] + o[1] * o[1] + o[2] * o[2] + o[3] * o[3];
        #pragma unroll
        for (int off = 8; off > 0; off >>= 1)
            ss += __shfl_xor_sync(0xffffffffu, ss, off);   // stays within 16-lane half
        float inv = 1.0f / fmaxf(sqrtf(ss), 1e-12f);
        if (valid[r]) {
            float4 ov = make_float4(o[0] * inv, o[1] * inv, o[2] * inv, o[3] * inv);
            reinterpret_cast<float4*>(out)[(size_t)node[r] * 16 + jj] = ov;
        }
    }

    // Self-clean scratch for the next launch. All reads of these rows happened
    // above in this same 16-thread group; the shuffles ordered them.
    float4* S4 = reinterpret_cast<float4*>(g_S);
    #pragma unroll
    for (int r = 0; r < 4; r++) {
        if (valid[r]) {
            S4[(size_t)node[r] * 16 + jj] = make_float4(0.f, 0.f, 0.f, 0.f);
            if (jj == 0) g_deg[node[r]] = 0.f;
        }
    }
}

// ---------------- launch ----------------------------------------------------
extern "C" void kernel_launch(void* const* d_in, const int* in_sizes, int n_in,
                              void* d_out, int out_size) {
    const float* x  = (const float*)d_in[0];
    const int*   ei = (const int*)d_in[1];
    const float* wm = (const float*)d_in[2];
    const float* bm = (const float*)d_in[3];
    const float* ws = (const float*)d_in[4];
    const float* bs = (const float*)d_in[5];
    const float* lc = (const float*)d_in[6];
    float* out = (float*)d_out;

    // collapse bases into packed weights (now parallel: 17 blocks)
    weights_kernel<<<17, 256>>>(wm, bm, ws, bs, lc);
    // edge scatter (g_S/g_deg are zero: BSS init on first call, self-cleaned after)
    {
        long long tot = (long long)E_HALF * 16;            // 10M threads
        int blocks = (int)((tot + 255) / 256);
        scatter_kernel<<<blocks, 256>>>((const float4*)x, ei);
    }
    // fused GEMM + bias + normalize + scratch self-clean
    out_kernel<<<N_TILES, 256>>>(x, out);
}